// round 15
// baseline (speedup 1.0000x reference)
#include <cuda_runtime.h>
#include <cuda_fp16.h>
#include <math.h>
#include <stdint.h>

// Problem shape (fixed)
#define B_  2
#define T_  2048
#define D_  1024
#define H_  16
#define HD_ 64
#define M_  (B_*T_)   // 4096

// ---------------------------------------------------------------------------
// Scratch (__device__ globals)
// GEMM-tiled: 8KB blocks = 128 rows x 32 halves, SW64 (g_XH/XL, g_CH, g_WT16)
// FLASH-tiled: per (b,h), 32 tiles of 64 tokens x 64 halves (8KB), SW128
// ---------------------------------------------------------------------------
__device__ __half g_XH[(size_t)M_ * D_];
__device__ __half g_XL[(size_t)M_ * D_];
__device__ __half g_QH[(size_t)M_ * D_];
__device__ __half g_QL[(size_t)M_ * D_];
__device__ __half g_KH[(size_t)M_ * D_];
__device__ __half g_KL[(size_t)M_ * D_];
__device__ __half g_VH[(size_t)M_ * D_];
__device__ __half g_VL[(size_t)M_ * D_];
__device__ __half g_CH[(size_t)M_ * D_];
// [0]=WqH [1]=WkH [2]=WvH [3]=WqL [4]=WkL [5]=WvL [6]=WoH [7]=WoL
__device__ __half g_WT16[8][(size_t)D_ * D_];

// ---------------------------------------------------------------------------
// PTX helpers
// ---------------------------------------------------------------------------
__device__ __forceinline__ uint32_t smem_u32(const void* p) {
    uint32_t a;
    asm("{ .reg .u64 t; cvta.to.shared.u64 t, %1; cvt.u32.u64 %0, t; }"
        : "=r"(a) : "l"(p));
    return a;
}

__device__ __forceinline__ void bulk_g2s(uint32_t sdst, const void* gsrc,
                                         uint32_t bytes, uint32_t mbar) {
    asm volatile(
        "cp.async.bulk.shared::cluster.global.mbarrier::complete_tx::bytes "
        "[%0], [%1], %2, [%3];"
        :: "r"(sdst), "l"(gsrc), "r"(bytes), "r"(mbar) : "memory");
}

#define MBAR_INIT(addr, cnt) \
    asm volatile("mbarrier.init.shared.b64 [%0], %1;" :: "r"(addr), "r"(cnt) : "memory")
#define MBAR_EXPECT(addr, bytes) \
    asm volatile("mbarrier.arrive.expect_tx.shared.b64 _, [%0], %1;" \
                 :: "r"(addr), "r"(bytes) : "memory")
#define MBAR_ARRIVE(addr) \
    asm volatile("mbarrier.arrive.shared.b64 _, [%0];" :: "r"(addr) : "memory")
#define MBAR_WAIT(addr, par) do {                                                  \
    uint32_t _m = (uint32_t)(addr); uint32_t _p = (uint32_t)(par);                 \
    asm volatile("{\n\t.reg .pred P1;\n\t"                                         \
        "WL_%=:\n\t"                                                                \
        "mbarrier.try_wait.parity.acquire.cta.shared::cta.b64 P1, [%0], %1;\n\t"   \
        "@P1 bra.uni WD_%=;\n\t"                                                    \
        "bra.uni WL_%=;\n\t"                                                        \
        "WD_%=:\n\t}" :: "r"(_m), "r"(_p) : "memory");                              \
} while (0)

__device__ __forceinline__ void ldm4(uint32_t* r, uint32_t addr) {
    asm volatile("ldmatrix.sync.aligned.m8n8.x4.shared.b16 {%0,%1,%2,%3}, [%4];"
                 : "=r"(r[0]), "=r"(r[1]), "=r"(r[2]), "=r"(r[3]) : "r"(addr));
}

__device__ __forceinline__ void ldm4t(uint32_t* r, uint32_t addr) {
    asm volatile("ldmatrix.sync.aligned.m8n8.x4.trans.shared.b16 {%0,%1,%2,%3}, [%4];"
                 : "=r"(r[0]), "=r"(r[1]), "=r"(r[2]), "=r"(r[3]) : "r"(addr));
}

__device__ __forceinline__ void mma16816(float* d, const uint32_t* a,
                                         uint32_t b0, uint32_t b1) {
    asm volatile(
        "mma.sync.aligned.m16n8k16.row.col.f32.f16.f16.f32 "
        "{%0,%1,%2,%3},{%4,%5,%6,%7},{%8,%9},{%0,%1,%2,%3};"
        : "+f"(d[0]), "+f"(d[1]), "+f"(d[2]), "+f"(d[3])
        : "r"(a[0]), "r"(a[1]), "r"(a[2]), "r"(a[3]), "r"(b0), "r"(b1));
}

__device__ __forceinline__ uint32_t h2_bits(__half2 v) {
    return *(uint32_t*)&v;
}

// GEMM-tiled offset (128-row x 32-col blocks, SW64)
__device__ __forceinline__ size_t tiled_off(int m, int col) {
    int blk = ((m >> 7) << 5) + (col >> 5);
    int r = m & 127, cb = col & 31;
    int chunk = (cb >> 3) ^ ((r >> 1) & 3);
    return (size_t)blk * 4096 + r * 32 + (chunk << 3) + (cb & 7);
}

// ---------------------------------------------------------------------------
// Prepass 1: fp32 -> (fp16 hi, lo), GEMM-tiled
// ---------------------------------------------------------------------------
__global__ void split16_kernel(const float4* __restrict__ in,
                               __half* __restrict__ hi, __half* __restrict__ lo,
                               int n4) {
    int i = blockIdx.x * blockDim.x + threadIdx.x;
    if (i >= n4) return;
    float4 v = in[i];
    __half hx = __float2half_rn(v.x), hy = __float2half_rn(v.y);
    __half hz = __float2half_rn(v.z), hw = __float2half_rn(v.w);
    __half lx = __float2half_rn(v.x - __half2float(hx));
    __half ly = __float2half_rn(v.y - __half2float(hy));
    __half lz = __float2half_rn(v.z - __half2float(hz));
    __half lw = __float2half_rn(v.w - __half2float(hw));
    __half2 h0 = __halves2half2(hx, hy), h1 = __halves2half2(hz, hw);
    __half2 l0 = __halves2half2(lx, ly), l1 = __halves2half2(lz, lw);
    int e = i * 4;
    int m = e >> 10, col = e & 1023;
    size_t off = tiled_off(m, col);
    *(uint2*)&hi[off] = make_uint2(h2_bits(h0), h2_bits(h1));
    *(uint2*)&lo[off] = make_uint2(h2_bits(l0), h2_bits(l1));
}

// ---------------------------------------------------------------------------
// Prepass 2: W[k][n] -> GEMM-tiled WT_hi[n][k], WT_lo[n][k]
// ---------------------------------------------------------------------------
__global__ void transpose_split16_all(const float* __restrict__ Wq,
                                      const float* __restrict__ Wk,
                                      const float* __restrict__ Wv,
                                      const float* __restrict__ Wo,
                                      __half* __restrict__ baseW) {
    __shared__ float t[32][33];
    const int z = blockIdx.z;
    const float* W = (z == 0) ? Wq : (z == 1) ? Wk : (z == 2) ? Wv : Wo;
    const size_t WSZ = (size_t)D_ * D_;
    __half* TH = baseW + ((z < 3) ? (size_t)z * WSZ : 6 * WSZ);
    __half* TL = baseW + ((z < 3) ? (size_t)(3 + z) * WSZ : 7 * WSZ);

    const int tx = threadIdx.x, ty = threadIdx.y;   // 32 x 8
    const int bn = blockIdx.x * 32;
    const int bk = blockIdx.y * 32;
#pragma unroll
    for (int i = 0; i < 4; i++)
        t[ty + 8 * i][tx] = W[(size_t)(bk + ty + 8 * i) * D_ + bn + tx];
    __syncthreads();
#pragma unroll
    for (int i = 0; i < 4; i++) {
        int row = ty + 8 * i;
        float v = t[tx][row];
        __half h = __float2half_rn(v);
        size_t o = tiled_off(bn + row, bk + tx);
        TH[o] = h;
        TL[o] = __float2half_rn(v - __half2float(h));
    }
}

// ---------------------------------------------------------------------------
// Bulk-copy GEMM with full/empty mbarrier ring (R14-verified).
// FOUT: 0 = fp32 row-major (+bias), 1 = flash-tiled fp16 (hi,lo), dual-output.
// ---------------------------------------------------------------------------
#define G_BLK    8192
#define G_STGB   (4 * G_BLK)
#define G_NSTG   3
#define G_SMEM   (G_NSTG * G_STGB + 128)
#define G_NCH    (D_ / 32)

template<int TERMS, int FOUT>
__global__ void __launch_bounds__(256, 2) gemm16_kernel(
    const __half* __restrict__ AH, const __half* __restrict__ AL,
    const __half* __restrict__ BH, const __half* __restrict__ BL,
    const float* __restrict__ bias, float scale, float scaleAlt,
    float* __restrict__ outF,
    __half* __restrict__ oH0, __half* __restrict__ oL0,
    __half* __restrict__ oH1, __half* __restrict__ oL1)
{
    extern __shared__ char smem[];
    const uint32_t sb  = smem_u32(smem);
    const uint32_t bar = sb + G_NSTG * G_STGB;
    const uint32_t ebar = bar + 24;
    const int tid = threadIdx.x;
    const int lid = tid & 31;
    const int wid = tid >> 5;
    const int wm  = wid >> 2;
    const int wn  = wid & 3;
    const int row16 = lid & 15;
    const int sel   = lid >> 4;
    const int bm = blockIdx.y << 7;
    const int bn = blockIdx.x << 7;
    const int aBlk = blockIdx.y << 5;
    const int bBlk = blockIdx.x << 5;

    if (tid == 0) {
#pragma unroll
        for (int s = 0; s < G_NSTG; s++) {
            MBAR_INIT(bar + s * 8, 1);
            MBAR_INIT(ebar + s * 8, 256);
        }
    }
    __syncthreads();

    const uint32_t BYTES = (TERMS == 3) ? (uint32_t)G_STGB : (uint32_t)(3 * G_BLK);
    auto issue = [&](int c, int s) {
        uint32_t mb = bar + s * 8;
        uint32_t sd = sb + (uint32_t)s * G_STGB;
        MBAR_EXPECT(mb, BYTES);
        bulk_g2s(sd,              (const char*)AH + (size_t)(aBlk + c) * G_BLK, G_BLK, mb);
        if (TERMS == 3)
            bulk_g2s(sd + G_BLK,  (const char*)AL + (size_t)(aBlk + c) * G_BLK, G_BLK, mb);
        bulk_g2s(sd + 2 * G_BLK,  (const char*)BH + (size_t)(bBlk + c) * G_BLK, G_BLK, mb);
        bulk_g2s(sd + 3 * G_BLK,  (const char*)BL + (size_t)(bBlk + c) * G_BLK, G_BLK, mb);
    };

    if (tid == 0) { issue(0, 0); issue(1, 1); issue(2, 2); }

    float acc[4][4][4];
#pragma unroll
    for (int mi = 0; mi < 4; mi++)
#pragma unroll
        for (int ni = 0; ni < 4; ni++)
#pragma unroll
            for (int j = 0; j < 4; j++) acc[mi][ni][j] = 0.f;

    for (int c = 0; c < G_NCH; c++) {
        const int s = c % G_NSTG;
        MBAR_WAIT(bar + s * 8, (c / G_NSTG) & 1);

        const uint32_t sA = sb + (uint32_t)s * G_STGB;
        const uint32_t sB = sA + 2 * G_BLK;
#pragma unroll
        for (int kk = 0; kk < 2; kk++) {
            const int ch = kk * 2 + sel;
            uint32_t ah[4][4], al[4][4];
#pragma unroll
            for (int mi = 0; mi < 4; mi++) {
                int r = wm * 64 + mi * 16 + row16;
                uint32_t addr = sA + (uint32_t)(r * 64 + ((ch ^ ((r >> 1) & 3)) << 4));
                ldm4(ah[mi], addr);
                if (TERMS == 3) ldm4(al[mi], addr + G_BLK);
            }
            uint32_t bh[2][4], bl[2][4];
#pragma unroll
            for (int g = 0; g < 2; g++) {
                int r = wn * 32 + g * 16 + row16;
                uint32_t addr = sB + (uint32_t)(r * 64 + ((ch ^ ((r >> 1) & 3)) << 4));
                ldm4(bh[g], addr);
                ldm4(bl[g], addr + G_BLK);
            }
#pragma unroll
            for (int mi = 0; mi < 4; mi++)
#pragma unroll
                for (int ni = 0; ni < 4; ni++) {
                    const int g = ni >> 1, o = ni & 1;
                    mma16816(acc[mi][ni], ah[mi], bh[g][o], bh[g][o + 2]);
                    mma16816(acc[mi][ni], ah[mi], bl[g][o], bl[g][o + 2]);
                    if (TERMS == 3)
                        mma16816(acc[mi][ni], al[mi], bh[g][o], bh[g][o + 2]);
                }
        }
        MBAR_ARRIVE(ebar + s * 8);
        if (tid == 0 && c + 3 < G_NCH) {
            const int cn = c + 3, sn = cn % G_NSTG;
            MBAR_WAIT(ebar + sn * 8, (cn / G_NSTG - 1) & 1);
            issue(cn, sn);
        }
    }

    if (FOUT == 0) {
#pragma unroll
        for (int mi = 0; mi < 4; mi++)
#pragma unroll
            for (int ni = 0; ni < 4; ni++) {
                int row = bm + wm * 64 + mi * 16 + (lid >> 2);
                int col = bn + wn * 32 + ni * 8 + (lid & 3) * 2;
                float v0 = acc[mi][ni][0] * scale, v1 = acc[mi][ni][1] * scale;
                float v2 = acc[mi][ni][2] * scale, v3 = acc[mi][ni][3] * scale;
                float b0 = bias ? bias[col] : 0.f, b1 = bias ? bias[col + 1] : 0.f;
                *(float2*)&outF[(size_t)row * D_ + col]       = make_float2(v0 + b0, v1 + b1);
                *(float2*)&outF[(size_t)(row + 8) * D_ + col] = make_float2(v2 + b0, v3 + b1);
            }
    } else {
        const int second = bn >> 10;
        const int nb = bn & 1023;
        const float scl = second ? scaleAlt : scale;
        __half* outH = second ? oH1 : oH0;
        __half* outL = second ? oL1 : oL0;
        const int bq   = bm >> 11;
        const int trow = ((bm & 2047) >> 6) + wm;
        const int hcol = (nb + wn * 32) >> 6;
        const size_t tb = ((size_t)(((bq << 4) + hcol) * 32 + trow)) << 12;
        const int r0 = lid >> 2;
        const int d0 = ((wn & 1) << 5) + ((lid & 3) << 1);
#pragma unroll
        for (int mi = 0; mi < 4; mi++) {
            const int r = r0 + mi * 16;
            const uint32_t rsw = (uint32_t)(r & 7);
#pragma unroll
            for (int ni = 0; ni < 4; ni++) {
                const int d = d0 + ni * 8;
                size_t off = tb + (size_t)(r * 64)
                           + ((((uint32_t)(d >> 3) ^ rsw) << 3)) + (d & 7);
                float v0 = acc[mi][ni][0] * scl, v1 = acc[mi][ni][1] * scl;
                float v2 = acc[mi][ni][2] * scl, v3 = acc[mi][ni][3] * scl;
                __half2 h0 = __floats2half2_rn(v0, v1);
                __half2 h1 = __floats2half2_rn(v2, v3);
                *(__half2*)&outH[off]       = h0;
                *(__half2*)&outH[off + 512] = h1;
                if (outL) {
                    __half2 l0 = __floats2half2_rn(v0 - __low2float(h0), v1 - __high2float(h0));
                    __half2 l1 = __floats2half2_rn(v2 - __low2float(h1), v3 - __high2float(h1));
                    *(__half2*)&outL[off]       = l0;
                    *(__half2*)&outL[off + 512] = l1;
                }
            }
        }
    }
}

// ---------------------------------------------------------------------------
// Flash attention: BM=64, 3-term S, 2-term PV, big-first, bulk-copy K/V.
// Smem ALIASED for 3 CTAs/SM (64KB): Q region reused by stage 1 after the
// one-time Q fragment extraction.
//   [0..16K):  Q (then stage1 KH@0, KL@8K)
//   [16..48K): stage0 KH,KL,VH,VL
//   [48..64K): stage1 VH,VL
// ---------------------------------------------------------------------------
#define F_TILE 8192
#define F_STGB (4 * F_TILE)
#define F_SMEM (8 * F_TILE + 128)   // 65664

__global__ void __launch_bounds__(128, 3) flash16_kernel(
    const __half* __restrict__ QH, const __half* __restrict__ QL,
    const __half* __restrict__ KH, const __half* __restrict__ KL,
    const __half* __restrict__ VH, const __half* __restrict__ VL,
    __half* __restrict__ CH)
{
    extern __shared__ char fsm[];
    const uint32_t sb  = smem_u32(fsm);
    const uint32_t bar = sb + 8 * F_TILE;  // q@0, full[2]@8,16, empty[2]@24,32
    const int qt = (int)gridDim.x - 1 - (int)blockIdx.x;
    const int bh = blockIdx.y;
    const int b = bh >> 4, h = bh & 15;
    const int tid = threadIdx.x, wid = tid >> 5, lid = tid & 31;
    const size_t fb = ((size_t)bh) << 17;

    if (tid == 0) {
        MBAR_INIT(bar, 1);
        MBAR_INIT(bar + 8, 1);  MBAR_INIT(bar + 16, 1);
        MBAR_INIT(bar + 24, 128); MBAR_INIT(bar + 32, 128);
    }
    __syncthreads();

    // Per-stage K/V bases (stage1 aliases the Q region for K)
    auto kbase = [&](int s) -> uint32_t { return s ? sb : sb + 2 * F_TILE; };
    auto vbase = [&](int s) -> uint32_t { return s ? sb + 6 * F_TILE : sb + 4 * F_TILE; };

    auto issue_kv = [&](int kt, int s) {
        uint32_t mb = bar + 8 + s * 8;
        size_t go = (fb + ((size_t)kt << 12)) * 2;
        MBAR_EXPECT(mb, F_STGB);
        uint32_t kb = kbase(s), vb = vbase(s);
        bulk_g2s(kb,          (const char*)KH + go, F_TILE, mb);
        bulk_g2s(kb + F_TILE, (const char*)KL + go, F_TILE, mb);
        bulk_g2s(vb,          (const char*)VH + go, F_TILE, mb);
        bulk_g2s(vb + F_TILE, (const char*)VL + go, F_TILE, mb);
    };

    if (tid == 0) {
        size_t qo = (fb + ((size_t)qt << 12)) * 2;
        MBAR_EXPECT(bar, 2 * F_TILE);
        bulk_g2s(sb,          (const char*)QH + qo, F_TILE, bar);
        bulk_g2s(sb + F_TILE, (const char*)QL + qo, F_TILE, bar);
        issue_kv(0, 0);       // stage0 does not alias Q
    }

    // Q fragments (register-resident); must complete before stage1 overwrites Q
    MBAR_WAIT(bar, 0);
    uint32_t qfh[4][4], qfl[4][4];
    {
        int r = wid * 16 + (lid & 15);
#pragma unroll
        for (int dc = 0; dc < 4; dc++) {
            int gran = dc * 2 + (lid >> 4);
            uint32_t a = sb + (uint32_t)(r * 128 + ((gran ^ (r & 7)) << 4));
            ldm4(qfh[dc], a);
            ldm4(qfl[dc], a + F_TILE);
        }
    }
    __syncthreads();           // all warps extracted Q
    if (tid == 0 && qt >= 1) issue_kv(1, 1);

    float oacc[8][4];
    float m_[2] = {-INFINITY, -INFINITY}, l_[2] = {0.f, 0.f};
#pragma unroll
    for (int ni = 0; ni < 8; ni++)
#pragma unroll
        for (int j = 0; j < 4; j++) oacc[ni][j] = 0.f;

    for (int kt = 0; kt <= qt; kt++) {
        const int s = kt & 1;
        MBAR_WAIT(bar + 8 + s * 8, (kt >> 1) & 1);

        const uint32_t kb = kbase(s);
        const uint32_t vb = vbase(s);

        float sacc[8][4];
#pragma unroll
        for (int ni = 0; ni < 8; ni++)
#pragma unroll
            for (int j = 0; j < 4; j++) sacc[ni][j] = 0.f;

#pragma unroll
        for (int dc = 0; dc < 4; dc++) {
#pragma unroll
            for (int g = 0; g < 4; g++) {
                int rr = g * 16 + (lid & 7) + ((lid >> 4) & 1) * 8;
                int gran = dc * 2 + ((lid >> 3) & 1);
                uint32_t ka = kb + (uint32_t)(rr * 128 + ((gran ^ (rr & 7)) << 4));
                uint32_t kh4[4], kl4[4];
                ldm4(kh4, ka);
                ldm4(kl4, ka + F_TILE);
                mma16816(sacc[2 * g],     qfh[dc], kh4[0], kh4[1]);
                mma16816(sacc[2 * g],     qfh[dc], kl4[0], kl4[1]);
                mma16816(sacc[2 * g],     qfl[dc], kh4[0], kh4[1]);
                mma16816(sacc[2 * g + 1], qfh[dc], kh4[2], kh4[3]);
                mma16816(sacc[2 * g + 1], qfh[dc], kl4[2], kl4[3]);
                mma16816(sacc[2 * g + 1], qfl[dc], kh4[2], kh4[3]);
            }
        }

        if (kt == qt) {
            int r0 = wid * 16 + (lid >> 2);
#pragma unroll
            for (int ni = 0; ni < 8; ni++) {
                int c0 = ni * 8 + (lid & 3) * 2;
                if (c0     > r0)     sacc[ni][0] = -INFINITY;
                if (c0 + 1 > r0)     sacc[ni][1] = -INFINITY;
                if (c0     > r0 + 8) sacc[ni][2] = -INFINITY;
                if (c0 + 1 > r0 + 8) sacc[ni][3] = -INFINITY;
            }
        }

#pragma unroll
        for (int r = 0; r < 2; r++) {
            float mt = -INFINITY;
#pragma unroll
            for (int ni = 0; ni < 8; ni++)
                mt = fmaxf(mt, fmaxf(sacc[ni][2 * r], sacc[ni][2 * r + 1]));
            mt = fmaxf(mt, __shfl_xor_sync(0xffffffffu, mt, 1));
            mt = fmaxf(mt, __shfl_xor_sync(0xffffffffu, mt, 2));
            float mn = fmaxf(m_[r], mt);
            float sc = __expf(m_[r] - mn);
            float ps = 0.f;
#pragma unroll
            for (int ni = 0; ni < 8; ni++) {
                float p0 = __expf(sacc[ni][2 * r]     - mn);
                float p1 = __expf(sacc[ni][2 * r + 1] - mn);
                sacc[ni][2 * r] = p0; sacc[ni][2 * r + 1] = p1;
                ps += p0 + p1;
            }
            ps += __shfl_xor_sync(0xffffffffu, ps, 1);
            ps += __shfl_xor_sync(0xffffffffu, ps, 2);
            l_[r] = l_[r] * sc + ps;
            m_[r] = mn;
#pragma unroll
            for (int ni = 0; ni < 8; ni++) {
                oacc[ni][2 * r]     *= sc;
                oacc[ni][2 * r + 1] *= sc;
            }
        }

        uint32_t pah[4][4];
#pragma unroll
        for (int kc = 0; kc < 4; kc++) {
#pragma unroll
            for (int q = 0; q < 4; q++) {
                int ni = 2 * kc + (q >> 1);
                __half2 hp = __floats2half2_rn(sacc[ni][(q & 1) * 2],
                                               sacc[ni][(q & 1) * 2 + 1]);
                pah[kc][q] = h2_bits(hp);
            }
        }

#pragma unroll
        for (int kc = 0; kc < 4; kc++) {
#pragma unroll
            for (int g = 0; g < 4; g++) {
                int rv = kc * 16 + (lid & 7) + ((lid >> 3) & 1) * 8;
                int gran = g * 2 + (lid >> 4);
                uint32_t va = vb + (uint32_t)(rv * 128 + ((gran ^ (rv & 7)) << 4));
                uint32_t vh4[4], vl4[4];
                ldm4t(vh4, va);
                ldm4t(vl4, va + F_TILE);
                mma16816(oacc[2 * g],     pah[kc], vh4[0], vh4[1]);
                mma16816(oacc[2 * g],     pah[kc], vl4[0], vl4[1]);
                mma16816(oacc[2 * g + 1], pah[kc], vh4[2], vh4[3]);
                mma16816(oacc[2 * g + 1], pah[kc], vl4[2], vl4[3]);
            }
        }

        MBAR_ARRIVE(bar + 24 + s * 8);
        if (tid == 0 && kt + 2 <= qt) {
            MBAR_WAIT(bar + 24 + s * 8, (kt >> 1) & 1);
            issue_kv(kt + 2, s);
        }
    }

    float inv0 = 1.f / l_[0], inv1 = 1.f / l_[1];
    int m0 = b * T_ + qt * 64 + wid * 16 + (lid >> 2);
#pragma unroll
    for (int ni = 0; ni < 8; ni++) {
        int colD = h * HD_ + ni * 8 + (lid & 3) * 2;
        __half2 h0 = __floats2half2_rn(oacc[ni][0] * inv0, oacc[ni][1] * inv0);
        __half2 h1 = __floats2half2_rn(oacc[ni][2] * inv1, oacc[ni][3] * inv1);
        *(__half2*)&CH[tiled_off(m0,     colD)] = h0;
        *(__half2*)&CH[tiled_off(m0 + 8, colD)] = h1;
    }
}

// ---------------------------------------------------------------------------
extern "C" void kernel_launch(void* const* d_in, const int* in_sizes, int n_in,
                              void* d_out, int out_size)
{
    const float* X  = (const float*)d_in[0];
    const float* Wq = (const float*)d_in[1];
    const float* Wk = (const float*)d_in[2];
    const float* Wv = (const float*)d_in[3];
    const float* Wo = (const float*)d_in[4];
    const float* bo = (const float*)d_in[5];
    float* Y = (float*)d_out;

    __half *gXH, *gXL, *gQH, *gQL, *gKH, *gKL, *gVH, *gVL, *gCH, *gWT;
    cudaGetSymbolAddress((void**)&gXH, g_XH);
    cudaGetSymbolAddress((void**)&gXL, g_XL);
    cudaGetSymbolAddress((void**)&gQH, g_QH);
    cudaGetSymbolAddress((void**)&gQL, g_QL);
    cudaGetSymbolAddress((void**)&gKH, g_KH);
    cudaGetSymbolAddress((void**)&gKL, g_KL);
    cudaGetSymbolAddress((void**)&gVH, g_VH);
    cudaGetSymbolAddress((void**)&gVL, g_VL);
    cudaGetSymbolAddress((void**)&gCH, g_CH);
    cudaGetSymbolAddress((void**)&gWT, g_WT16);
    const size_t WSZ = (size_t)D_ * D_;

    cudaFuncSetAttribute((const void*)gemm16_kernel<3, 1>,
                         cudaFuncAttributeMaxDynamicSharedMemorySize, G_SMEM);
    cudaFuncSetAttribute((const void*)gemm16_kernel<2, 1>,
                         cudaFuncAttributeMaxDynamicSharedMemorySize, G_SMEM);
    cudaFuncSetAttribute((const void*)gemm16_kernel<2, 0>,
                         cudaFuncAttributeMaxDynamicSharedMemorySize, G_SMEM);
    cudaFuncSetAttribute((const void*)flash16_kernel,
                         cudaFuncAttributeMaxDynamicSharedMemorySize, F_SMEM);

    const int n4 = (M_ * D_) / 4;
    split16_kernel<<<(n4 + 255) / 256, 256>>>((const float4*)X, gXH, gXL, n4);
    transpose_split16_all<<<dim3(32, 32, 4), dim3(32, 8)>>>(Wq, Wk, Wv, Wo, gWT);

    // Fused Q+K projection (3-term); V projection (2-term)
    gemm16_kernel<3, 1><<<dim3(2 * D_ / 128, M_ / 128), 256, G_SMEM>>>(
        gXH, gXL, gWT + 0 * WSZ, gWT + 3 * WSZ,
        nullptr, 0.125f, 1.0f, nullptr, gQH, gQL, gKH, gKL);
    gemm16_kernel<2, 1><<<dim3(D_ / 128, M_ / 128), 256, G_SMEM>>>(
        gXH, gXL, gWT + 2 * WSZ, gWT + 5 * WSZ,
        nullptr, 1.0f, 1.0f, nullptr, gVH, gVL, gVH, gVL);

    flash16_kernel<<<dim3(T_ / 64, B_ * H_), 128, F_SMEM>>>(
        gQH, gQL, gKH, gKL, gVH, gVL, gCH);

    // Output projection (2-term, fp32 out + bias)
    gemm16_kernel<2, 0><<<dim3(D_ / 128, M_ / 128), 256, G_SMEM>>>(
        gCH, nullptr, gWT + 6 * WSZ, gWT + 7 * WSZ,
        bo, 1.0f, 1.0f, Y, nullptr, nullptr, nullptr, nullptr);
}

// round 16
// speedup vs baseline: 1.0117x; 1.0117x over previous
#include <cuda_runtime.h>
#include <cuda_fp16.h>
#include <math.h>
#include <stdint.h>

// Problem shape (fixed)
#define B_  2
#define T_  2048
#define D_  1024
#define H_  16
#define HD_ 64
#define M_  (B_*T_)   // 4096

// ---------------------------------------------------------------------------
// Scratch (__device__ globals)
// GEMM-tiled: 8KB blocks = 128 rows x 32 halves, SW64 (g_XH/XL, g_CH, g_WT16)
// FLASH-tiled: per (b,h), 32 tiles of 64 tokens x 64 halves (8KB), SW128
// ---------------------------------------------------------------------------
__device__ __half g_XH[(size_t)M_ * D_];
__device__ __half g_XL[(size_t)M_ * D_];
__device__ __half g_QH[(size_t)M_ * D_];
__device__ __half g_QL[(size_t)M_ * D_];
__device__ __half g_KH[(size_t)M_ * D_];
__device__ __half g_KL[(size_t)M_ * D_];
__device__ __half g_VH[(size_t)M_ * D_];
__device__ __half g_VL[(size_t)M_ * D_];
__device__ __half g_CH[(size_t)M_ * D_];
// [0]=WqH [1]=WkH [2]=WvH [3]=WqL [4]=WkL [5]=WvL [6]=WoH [7]=WoL
__device__ __half g_WT16[8][(size_t)D_ * D_];

// ---------------------------------------------------------------------------
// PTX helpers
// ---------------------------------------------------------------------------
__device__ __forceinline__ uint32_t smem_u32(const void* p) {
    uint32_t a;
    asm("{ .reg .u64 t; cvta.to.shared.u64 t, %1; cvt.u32.u64 %0, t; }"
        : "=r"(a) : "l"(p));
    return a;
}

__device__ __forceinline__ void bulk_g2s(uint32_t sdst, const void* gsrc,
                                         uint32_t bytes, uint32_t mbar) {
    asm volatile(
        "cp.async.bulk.shared::cluster.global.mbarrier::complete_tx::bytes "
        "[%0], [%1], %2, [%3];"
        :: "r"(sdst), "l"(gsrc), "r"(bytes), "r"(mbar) : "memory");
}

#define MBAR_INIT(addr, cnt) \
    asm volatile("mbarrier.init.shared.b64 [%0], %1;" :: "r"(addr), "r"(cnt) : "memory")
#define MBAR_EXPECT(addr, bytes) \
    asm volatile("mbarrier.arrive.expect_tx.shared.b64 _, [%0], %1;" \
                 :: "r"(addr), "r"(bytes) : "memory")
#define MBAR_ARRIVE(addr) \
    asm volatile("mbarrier.arrive.shared.b64 _, [%0];" :: "r"(addr) : "memory")
#define MBAR_WAIT(addr, par) do {                                                  \
    uint32_t _m = (uint32_t)(addr); uint32_t _p = (uint32_t)(par);                 \
    asm volatile("{\n\t.reg .pred P1;\n\t"                                         \
        "WL_%=:\n\t"                                                                \
        "mbarrier.try_wait.parity.acquire.cta.shared::cta.b64 P1, [%0], %1;\n\t"   \
        "@P1 bra.uni WD_%=;\n\t"                                                    \
        "bra.uni WL_%=;\n\t"                                                        \
        "WD_%=:\n\t}" :: "r"(_m), "r"(_p) : "memory");                              \
} while (0)

__device__ __forceinline__ void ldm4(uint32_t* r, uint32_t addr) {
    asm volatile("ldmatrix.sync.aligned.m8n8.x4.shared.b16 {%0,%1,%2,%3}, [%4];"
                 : "=r"(r[0]), "=r"(r[1]), "=r"(r[2]), "=r"(r[3]) : "r"(addr));
}

__device__ __forceinline__ void ldm4t(uint32_t* r, uint32_t addr) {
    asm volatile("ldmatrix.sync.aligned.m8n8.x4.trans.shared.b16 {%0,%1,%2,%3}, [%4];"
                 : "=r"(r[0]), "=r"(r[1]), "=r"(r[2]), "=r"(r[3]) : "r"(addr));
}

__device__ __forceinline__ void mma16816(float* d, const uint32_t* a,
                                         uint32_t b0, uint32_t b1) {
    asm volatile(
        "mma.sync.aligned.m16n8k16.row.col.f32.f16.f16.f32 "
        "{%0,%1,%2,%3},{%4,%5,%6,%7},{%8,%9},{%0,%1,%2,%3};"
        : "+f"(d[0]), "+f"(d[1]), "+f"(d[2]), "+f"(d[3])
        : "r"(a[0]), "r"(a[1]), "r"(a[2]), "r"(a[3]), "r"(b0), "r"(b1));
}

__device__ __forceinline__ uint32_t h2_bits(__half2 v) {
    return *(uint32_t*)&v;
}

// GEMM-tiled offset (128-row x 32-col blocks, SW64)
__device__ __forceinline__ size_t tiled_off(int m, int col) {
    int blk = ((m >> 7) << 5) + (col >> 5);
    int r = m & 127, cb = col & 31;
    int chunk = (cb >> 3) ^ ((r >> 1) & 3);
    return (size_t)blk * 4096 + r * 32 + (chunk << 3) + (cb & 7);
}

// ---------------------------------------------------------------------------
// Prepass 1: fp32 -> (fp16 hi, lo), GEMM-tiled. 8 elems/thread, uint4 stores.
// col = (i*8) & 1023 is 8-aligned -> one contiguous 16B granule in the tiling.
// ---------------------------------------------------------------------------
__global__ void split16_kernel(const float4* __restrict__ in,
                               __half* __restrict__ hi, __half* __restrict__ lo,
                               int n8) {
    int i = blockIdx.x * blockDim.x + threadIdx.x;
    if (i >= n8) return;
    float4 a = in[2 * i], b = in[2 * i + 1];
    float v[8] = {a.x, a.y, a.z, a.w, b.x, b.y, b.z, b.w};
    __half hh[8], ll[8];
#pragma unroll
    for (int j = 0; j < 8; j++) {
        hh[j] = __float2half_rn(v[j]);
        ll[j] = __float2half_rn(v[j] - __half2float(hh[j]));
    }
    int e = i * 8;
    int m = e >> 10, col = e & 1023;
    size_t off = tiled_off(m, col);
    *(uint4*)&hi[off] = *(uint4*)hh;
    *(uint4*)&lo[off] = *(uint4*)ll;
}

// ---------------------------------------------------------------------------
// Prepass 2: W[k][n] -> GEMM-tiled WT_hi[n][k], WT_lo[n][k], uint4 stores.
// Write mapping: 256 threads = 32 n-rows x 4 k-granules x 2 parts (hi/lo).
// ---------------------------------------------------------------------------
__global__ void transpose_split16_all(const float* __restrict__ Wq,
                                      const float* __restrict__ Wk,
                                      const float* __restrict__ Wv,
                                      const float* __restrict__ Wo,
                                      __half* __restrict__ baseW) {
    __shared__ float t[32][33];
    const int z = blockIdx.z;
    const float* W = (z == 0) ? Wq : (z == 1) ? Wk : (z == 2) ? Wv : Wo;
    const size_t WSZ = (size_t)D_ * D_;
    __half* TH = baseW + ((z < 3) ? (size_t)z * WSZ : 6 * WSZ);
    __half* TL = baseW + ((z < 3) ? (size_t)(3 + z) * WSZ : 7 * WSZ);

    const int tid = threadIdx.x;                 // 256
    const int tx = tid & 31, ty = tid >> 5;      // loaders: 32 x 8
    const int bn = blockIdx.x * 32;
    const int bk = blockIdx.y * 32;
#pragma unroll
    for (int i = 0; i < 4; i++)
        t[ty + 8 * i][tx] = W[(size_t)(bk + ty + 8 * i) * D_ + bn + tx];
    __syncthreads();

    const int row  = tid & 31;                   // n within tile
    const int gran = (tid >> 5) & 3;             // k granule (8 k's)
    const int part = tid >> 7;                   // 0 = hi, 1 = lo
    __half buf[8];
    if (part == 0) {
#pragma unroll
        for (int j = 0; j < 8; j++)
            buf[j] = __float2half_rn(t[gran * 8 + j][row]);
        *(uint4*)&TH[tiled_off(bn + row, bk + gran * 8)] = *(uint4*)buf;
    } else {
#pragma unroll
        for (int j = 0; j < 8; j++) {
            float v = t[gran * 8 + j][row];
            __half h = __float2half_rn(v);
            buf[j] = __float2half_rn(v - __half2float(h));
        }
        *(uint4*)&TL[tiled_off(bn + row, bk + gran * 8)] = *(uint4*)buf;
    }
}

// ---------------------------------------------------------------------------
// Bulk-copy GEMM with full/empty mbarrier ring (R14-verified).
// FOUT: 0 = fp32 row-major (+bias), 1 = flash-tiled fp16 (hi,lo), dual-output.
// ---------------------------------------------------------------------------
#define G_BLK    8192
#define G_STGB   (4 * G_BLK)
#define G_NSTG   3
#define G_SMEM   (G_NSTG * G_STGB + 128)
#define G_NCH    (D_ / 32)

template<int TERMS, int FOUT>
__global__ void __launch_bounds__(256, 2) gemm16_kernel(
    const __half* __restrict__ AH, const __half* __restrict__ AL,
    const __half* __restrict__ BH, const __half* __restrict__ BL,
    const float* __restrict__ bias, float scale, float scaleAlt,
    float* __restrict__ outF,
    __half* __restrict__ oH0, __half* __restrict__ oL0,
    __half* __restrict__ oH1, __half* __restrict__ oL1)
{
    extern __shared__ char smem[];
    const uint32_t sb  = smem_u32(smem);
    const uint32_t bar = sb + G_NSTG * G_STGB;
    const uint32_t ebar = bar + 24;
    const int tid = threadIdx.x;
    const int lid = tid & 31;
    const int wid = tid >> 5;
    const int wm  = wid >> 2;
    const int wn  = wid & 3;
    const int row16 = lid & 15;
    const int sel   = lid >> 4;
    const int bm = blockIdx.y << 7;
    const int bn = blockIdx.x << 7;
    const int aBlk = blockIdx.y << 5;
    const int bBlk = blockIdx.x << 5;

    if (tid == 0) {
#pragma unroll
        for (int s = 0; s < G_NSTG; s++) {
            MBAR_INIT(bar + s * 8, 1);
            MBAR_INIT(ebar + s * 8, 256);
        }
    }
    __syncthreads();

    const uint32_t BYTES = (TERMS == 3) ? (uint32_t)G_STGB : (uint32_t)(3 * G_BLK);
    auto issue = [&](int c, int s) {
        uint32_t mb = bar + s * 8;
        uint32_t sd = sb + (uint32_t)s * G_STGB;
        MBAR_EXPECT(mb, BYTES);
        bulk_g2s(sd,              (const char*)AH + (size_t)(aBlk + c) * G_BLK, G_BLK, mb);
        if (TERMS == 3)
            bulk_g2s(sd + G_BLK,  (const char*)AL + (size_t)(aBlk + c) * G_BLK, G_BLK, mb);
        bulk_g2s(sd + 2 * G_BLK,  (const char*)BH + (size_t)(bBlk + c) * G_BLK, G_BLK, mb);
        bulk_g2s(sd + 3 * G_BLK,  (const char*)BL + (size_t)(bBlk + c) * G_BLK, G_BLK, mb);
    };

    if (tid == 0) { issue(0, 0); issue(1, 1); issue(2, 2); }

    float acc[4][4][4];
#pragma unroll
    for (int mi = 0; mi < 4; mi++)
#pragma unroll
        for (int ni = 0; ni < 4; ni++)
#pragma unroll
            for (int j = 0; j < 4; j++) acc[mi][ni][j] = 0.f;

    for (int c = 0; c < G_NCH; c++) {
        const int s = c % G_NSTG;
        MBAR_WAIT(bar + s * 8, (c / G_NSTG) & 1);

        const uint32_t sA = sb + (uint32_t)s * G_STGB;
        const uint32_t sB = sA + 2 * G_BLK;
#pragma unroll
        for (int kk = 0; kk < 2; kk++) {
            const int ch = kk * 2 + sel;
            uint32_t ah[4][4], al[4][4];
#pragma unroll
            for (int mi = 0; mi < 4; mi++) {
                int r = wm * 64 + mi * 16 + row16;
                uint32_t addr = sA + (uint32_t)(r * 64 + ((ch ^ ((r >> 1) & 3)) << 4));
                ldm4(ah[mi], addr);
                if (TERMS == 3) ldm4(al[mi], addr + G_BLK);
            }
            uint32_t bh[2][4], bl[2][4];
#pragma unroll
            for (int g = 0; g < 2; g++) {
                int r = wn * 32 + g * 16 + row16;
                uint32_t addr = sB + (uint32_t)(r * 64 + ((ch ^ ((r >> 1) & 3)) << 4));
                ldm4(bh[g], addr);
                ldm4(bl[g], addr + G_BLK);
            }
#pragma unroll
            for (int mi = 0; mi < 4; mi++)
#pragma unroll
                for (int ni = 0; ni < 4; ni++) {
                    const int g = ni >> 1, o = ni & 1;
                    mma16816(acc[mi][ni], ah[mi], bh[g][o], bh[g][o + 2]);
                    mma16816(acc[mi][ni], ah[mi], bl[g][o], bl[g][o + 2]);
                    if (TERMS == 3)
                        mma16816(acc[mi][ni], al[mi], bh[g][o], bh[g][o + 2]);
                }
        }
        MBAR_ARRIVE(ebar + s * 8);
        if (tid == 0 && c + 3 < G_NCH) {
            const int cn = c + 3, sn = cn % G_NSTG;
            MBAR_WAIT(ebar + sn * 8, (cn / G_NSTG - 1) & 1);
            issue(cn, sn);
        }
    }

    if (FOUT == 0) {
#pragma unroll
        for (int mi = 0; mi < 4; mi++)
#pragma unroll
            for (int ni = 0; ni < 4; ni++) {
                int row = bm + wm * 64 + mi * 16 + (lid >> 2);
                int col = bn + wn * 32 + ni * 8 + (lid & 3) * 2;
                float v0 = acc[mi][ni][0] * scale, v1 = acc[mi][ni][1] * scale;
                float v2 = acc[mi][ni][2] * scale, v3 = acc[mi][ni][3] * scale;
                float b0 = bias ? bias[col] : 0.f, b1 = bias ? bias[col + 1] : 0.f;
                *(float2*)&outF[(size_t)row * D_ + col]       = make_float2(v0 + b0, v1 + b1);
                *(float2*)&outF[(size_t)(row + 8) * D_ + col] = make_float2(v2 + b0, v3 + b1);
            }
    } else {
        const int second = bn >> 10;
        const int nb = bn & 1023;
        const float scl = second ? scaleAlt : scale;
        __half* outH = second ? oH1 : oH0;
        __half* outL = second ? oL1 : oL0;
        const int bq   = bm >> 11;
        const int trow = ((bm & 2047) >> 6) + wm;
        const int hcol = (nb + wn * 32) >> 6;
        const size_t tb = ((size_t)(((bq << 4) + hcol) * 32 + trow)) << 12;
        const int r0 = lid >> 2;
        const int d0 = ((wn & 1) << 5) + ((lid & 3) << 1);
#pragma unroll
        for (int mi = 0; mi < 4; mi++) {
            const int r = r0 + mi * 16;
            const uint32_t rsw = (uint32_t)(r & 7);
#pragma unroll
            for (int ni = 0; ni < 4; ni++) {
                const int d = d0 + ni * 8;
                size_t off = tb + (size_t)(r * 64)
                           + ((((uint32_t)(d >> 3) ^ rsw) << 3)) + (d & 7);
                float v0 = acc[mi][ni][0] * scl, v1 = acc[mi][ni][1] * scl;
                float v2 = acc[mi][ni][2] * scl, v3 = acc[mi][ni][3] * scl;
                __half2 h0 = __floats2half2_rn(v0, v1);
                __half2 h1 = __floats2half2_rn(v2, v3);
                *(__half2*)&outH[off]       = h0;
                *(__half2*)&outH[off + 512] = h1;
                if (outL) {
                    __half2 l0 = __floats2half2_rn(v0 - __low2float(h0), v1 - __high2float(h0));
                    __half2 l1 = __floats2half2_rn(v2 - __low2float(h1), v3 - __high2float(h1));
                    *(__half2*)&outL[off]       = l0;
                    *(__half2*)&outL[off + 512] = l1;
                }
            }
        }
    }
}

// ---------------------------------------------------------------------------
// Flash attention (R14-verified): BM=64, 3-term S, 2-term PV, big-first,
// bulk-copy K/V, SW128 flash tiles, full/empty mbarrier ring.
// ---------------------------------------------------------------------------
#define F_TILE 8192
#define F_QB   (2 * F_TILE)
#define F_STGB (4 * F_TILE)
#define F_SMEM (F_QB + 2 * F_STGB + 128)

__global__ void __launch_bounds__(128) flash16_kernel(
    const __half* __restrict__ QH, const __half* __restrict__ QL,
    const __half* __restrict__ KH, const __half* __restrict__ KL,
    const __half* __restrict__ VH, const __half* __restrict__ VL,
    __half* __restrict__ CH)
{
    extern __shared__ char fsm[];
    const uint32_t sb  = smem_u32(fsm);
    const uint32_t bar = sb + F_QB + 2 * F_STGB;  // q@0, full[2]@8,16, empty[2]@24,32
    const int qt = (int)gridDim.x - 1 - (int)blockIdx.x;
    const int bh = blockIdx.y;
    const int b = bh >> 4, h = bh & 15;
    const int tid = threadIdx.x, wid = tid >> 5, lid = tid & 31;
    const size_t fb = ((size_t)bh) << 17;

    if (tid == 0) {
        MBAR_INIT(bar, 1);
        MBAR_INIT(bar + 8, 1);  MBAR_INIT(bar + 16, 1);
        MBAR_INIT(bar + 24, 128); MBAR_INIT(bar + 32, 128);
    }
    __syncthreads();

    auto issue_kv = [&](int kt, int s) {
        uint32_t mb = bar + 8 + s * 8;
        uint32_t sd = sb + F_QB + (uint32_t)s * F_STGB;
        size_t go = (fb + ((size_t)kt << 12)) * 2;
        MBAR_EXPECT(mb, F_STGB);
        bulk_g2s(sd,              (const char*)KH + go, F_TILE, mb);
        bulk_g2s(sd + F_TILE,     (const char*)KL + go, F_TILE, mb);
        bulk_g2s(sd + 2 * F_TILE, (const char*)VH + go, F_TILE, mb);
        bulk_g2s(sd + 3 * F_TILE, (const char*)VL + go, F_TILE, mb);
    };

    if (tid == 0) {
        size_t qo = (fb + ((size_t)qt << 12)) * 2;
        MBAR_EXPECT(bar, F_QB);
        bulk_g2s(sb,          (const char*)QH + qo, F_TILE, bar);
        bulk_g2s(sb + F_TILE, (const char*)QL + qo, F_TILE, bar);
        issue_kv(0, 0);
        if (qt >= 1) issue_kv(1, 1);
    }

    MBAR_WAIT(bar, 0);
    uint32_t qfh[4][4], qfl[4][4];
    {
        int r = wid * 16 + (lid & 15);
#pragma unroll
        for (int dc = 0; dc < 4; dc++) {
            int gran = dc * 2 + (lid >> 4);
            uint32_t a = sb + (uint32_t)(r * 128 + ((gran ^ (r & 7)) << 4));
            ldm4(qfh[dc], a);
            ldm4(qfl[dc], a + F_TILE);
        }
    }

    float oacc[8][4];
    float m_[2] = {-INFINITY, -INFINITY}, l_[2] = {0.f, 0.f};
#pragma unroll
    for (int ni = 0; ni < 8; ni++)
#pragma unroll
        for (int j = 0; j < 4; j++) oacc[ni][j] = 0.f;

    for (int kt = 0; kt <= qt; kt++) {
        const int s = kt & 1;
        MBAR_WAIT(bar + 8 + s * 8, (kt >> 1) & 1);

        const uint32_t ks = sb + F_QB + (uint32_t)s * F_STGB;

        float sacc[8][4];
#pragma unroll
        for (int ni = 0; ni < 8; ni++)
#pragma unroll
            for (int j = 0; j < 4; j++) sacc[ni][j] = 0.f;

#pragma unroll
        for (int dc = 0; dc < 4; dc++) {
#pragma unroll
            for (int g = 0; g < 4; g++) {
                int rr = g * 16 + (lid & 7) + ((lid >> 4) & 1) * 8;
                int gran = dc * 2 + ((lid >> 3) & 1);
                uint32_t ka = ks + (uint32_t)(rr * 128 + ((gran ^ (rr & 7)) << 4));
                uint32_t kh4[4], kl4[4];
                ldm4(kh4, ka);
                ldm4(kl4, ka + F_TILE);
                mma16816(sacc[2 * g],     qfh[dc], kh4[0], kh4[1]);
                mma16816(sacc[2 * g],     qfh[dc], kl4[0], kl4[1]);
                mma16816(sacc[2 * g],     qfl[dc], kh4[0], kh4[1]);
                mma16816(sacc[2 * g + 1], qfh[dc], kh4[2], kh4[3]);
                mma16816(sacc[2 * g + 1], qfh[dc], kl4[2], kl4[3]);
                mma16816(sacc[2 * g + 1], qfl[dc], kh4[2], kh4[3]);
            }
        }

        if (kt == qt) {
            int r0 = wid * 16 + (lid >> 2);
#pragma unroll
            for (int ni = 0; ni < 8; ni++) {
                int c0 = ni * 8 + (lid & 3) * 2;
                if (c0     > r0)     sacc[ni][0] = -INFINITY;
                if (c0 + 1 > r0)     sacc[ni][1] = -INFINITY;
                if (c0     > r0 + 8) sacc[ni][2] = -INFINITY;
                if (c0 + 1 > r0 + 8) sacc[ni][3] = -INFINITY;
            }
        }

#pragma unroll
        for (int r = 0; r < 2; r++) {
            float mt = -INFINITY;
#pragma unroll
            for (int ni = 0; ni < 8; ni++)
                mt = fmaxf(mt, fmaxf(sacc[ni][2 * r], sacc[ni][2 * r + 1]));
            mt = fmaxf(mt, __shfl_xor_sync(0xffffffffu, mt, 1));
            mt = fmaxf(mt, __shfl_xor_sync(0xffffffffu, mt, 2));
            float mn = fmaxf(m_[r], mt);
            float sc = __expf(m_[r] - mn);
            float ps = 0.f;
#pragma unroll
            for (int ni = 0; ni < 8; ni++) {
                float p0 = __expf(sacc[ni][2 * r]     - mn);
                float p1 = __expf(sacc[ni][2 * r + 1] - mn);
                sacc[ni][2 * r] = p0; sacc[ni][2 * r + 1] = p1;
                ps += p0 + p1;
            }
            ps += __shfl_xor_sync(0xffffffffu, ps, 1);
            ps += __shfl_xor_sync(0xffffffffu, ps, 2);
            l_[r] = l_[r] * sc + ps;
            m_[r] = mn;
#pragma unroll
            for (int ni = 0; ni < 8; ni++) {
                oacc[ni][2 * r]     *= sc;
                oacc[ni][2 * r + 1] *= sc;
            }
        }

        uint32_t pah[4][4];
#pragma unroll
        for (int kc = 0; kc < 4; kc++) {
#pragma unroll
            for (int q = 0; q < 4; q++) {
                int ni = 2 * kc + (q >> 1);
                __half2 hp = __floats2half2_rn(sacc[ni][(q & 1) * 2],
                                               sacc[ni][(q & 1) * 2 + 1]);
                pah[kc][q] = h2_bits(hp);
            }
        }

        const uint32_t vs = ks + 2 * F_TILE;
#pragma unroll
        for (int kc = 0; kc < 4; kc++) {
#pragma unroll
            for (int g = 0; g < 4; g++) {
                int rv = kc * 16 + (lid & 7) + ((lid >> 3) & 1) * 8;
                int gran = g * 2 + (lid >> 4);
                uint32_t va = vs + (uint32_t)(rv * 128 + ((gran ^ (rv & 7)) << 4));
                uint32_t vh4[4], vl4[4];
                ldm4t(vh4, va);
                ldm4t(vl4, va + F_TILE);
                mma16816(oacc[2 * g],     pah[kc], vh4[0], vh4[1]);
                mma16816(oacc[2 * g],     pah[kc], vl4[0], vl4[1]);
                mma16816(oacc[2 * g + 1], pah[kc], vh4[2], vh4[3]);
                mma16816(oacc[2 * g + 1], pah[kc], vl4[2], vl4[3]);
            }
        }

        MBAR_ARRIVE(bar + 24 + s * 8);
        if (tid == 0 && kt + 2 <= qt) {
            MBAR_WAIT(bar + 24 + s * 8, (kt >> 1) & 1);
            issue_kv(kt + 2, s);
        }
    }

    float inv0 = 1.f / l_[0], inv1 = 1.f / l_[1];
    int m0 = b * T_ + qt * 64 + wid * 16 + (lid >> 2);
#pragma unroll
    for (int ni = 0; ni < 8; ni++) {
        int colD = h * HD_ + ni * 8 + (lid & 3) * 2;
        __half2 h0 = __floats2half2_rn(oacc[ni][0] * inv0, oacc[ni][1] * inv0);
        __half2 h1 = __floats2half2_rn(oacc[ni][2] * inv1, oacc[ni][3] * inv1);
        *(__half2*)&CH[tiled_off(m0,     colD)] = h0;
        *(__half2*)&CH[tiled_off(m0 + 8, colD)] = h1;
    }
}

// ---------------------------------------------------------------------------
extern "C" void kernel_launch(void* const* d_in, const int* in_sizes, int n_in,
                              void* d_out, int out_size)
{
    const float* X  = (const float*)d_in[0];
    const float* Wq = (const float*)d_in[1];
    const float* Wk = (const float*)d_in[2];
    const float* Wv = (const float*)d_in[3];
    const float* Wo = (const float*)d_in[4];
    const float* bo = (const float*)d_in[5];
    float* Y = (float*)d_out;

    __half *gXH, *gXL, *gQH, *gQL, *gKH, *gKL, *gVH, *gVL, *gCH, *gWT;
    cudaGetSymbolAddress((void**)&gXH, g_XH);
    cudaGetSymbolAddress((void**)&gXL, g_XL);
    cudaGetSymbolAddress((void**)&gQH, g_QH);
    cudaGetSymbolAddress((void**)&gQL, g_QL);
    cudaGetSymbolAddress((void**)&gKH, g_KH);
    cudaGetSymbolAddress((void**)&gKL, g_KL);
    cudaGetSymbolAddress((void**)&gVH, g_VH);
    cudaGetSymbolAddress((void**)&gVL, g_VL);
    cudaGetSymbolAddress((void**)&gCH, g_CH);
    cudaGetSymbolAddress((void**)&gWT, g_WT16);
    const size_t WSZ = (size_t)D_ * D_;

    cudaFuncSetAttribute((const void*)gemm16_kernel<3, 1>,
                         cudaFuncAttributeMaxDynamicSharedMemorySize, G_SMEM);
    cudaFuncSetAttribute((const void*)gemm16_kernel<2, 1>,
                         cudaFuncAttributeMaxDynamicSharedMemorySize, G_SMEM);
    cudaFuncSetAttribute((const void*)gemm16_kernel<2, 0>,
                         cudaFuncAttributeMaxDynamicSharedMemorySize, G_SMEM);
    cudaFuncSetAttribute((const void*)flash16_kernel,
                         cudaFuncAttributeMaxDynamicSharedMemorySize, F_SMEM);

    const int n8 = (M_ * D_) / 8;
    split16_kernel<<<(n8 + 255) / 256, 256>>>((const float4*)X, gXH, gXL, n8);
    transpose_split16_all<<<dim3(32, 32, 4), 256>>>(Wq, Wk, Wv, Wo, gWT);

    // Fused Q+K projection (3-term); V projection (2-term)
    gemm16_kernel<3, 1><<<dim3(2 * D_ / 128, M_ / 128), 256, G_SMEM>>>(
        gXH, gXL, gWT + 0 * WSZ, gWT + 3 * WSZ,
        nullptr, 0.125f, 1.0f, nullptr, gQH, gQL, gKH, gKL);
    gemm16_kernel<2, 1><<<dim3(D_ / 128, M_ / 128), 256, G_SMEM>>>(
        gXH, gXL, gWT + 2 * WSZ, gWT + 5 * WSZ,
        nullptr, 1.0f, 1.0f, nullptr, gVH, gVL, gVH, gVL);

    flash16_kernel<<<dim3(T_ / 64, B_ * H_), 128, F_SMEM>>>(
        gQH, gQL, gKH, gKL, gVH, gVL, gCH);

    // Output projection (2-term, fp32 out + bias)
    gemm16_kernel<2, 0><<<dim3(D_ / 128, M_ / 128), 256, G_SMEM>>>(
        gCH, nullptr, gWT + 6 * WSZ, gWT + 7 * WSZ,
        bo, 1.0f, 1.0f, Y, nullptr, nullptr, nullptr, nullptr);
}